// round 6
// baseline (speedup 1.0000x reference)
#include <cuda_runtime.h>
#include <math.h>
#include <stdint.h>

#define CB   8
#define PP   2048
#define DKx  256
#define BB   8192
#define TK   4

// output offsets (elements, fp32)
#define OFF_QV   0ULL
#define OFF_QK   67108864ULL
#define OFF_IND  134217728ULL
#define OFF_DIST 134479872ULL
#define OFF_CNT  134742016ULL
#define OFF_FLAT 135004160ULL

#define NSHORT 16          // final shortlist per row (refine input)
#define NTL    8           // per-thread shortlist in dist

__device__ int    g_idx[BB * CB * TK];
__device__ int    g_short[BB * CB * NSHORT];
__device__ float  g_knorm[CB * PP];
// keys transposed d-major, tf32-rounded: [(c*256 + d)*2048 + j]
__device__ float  g_kTT[CB * 256 * PP];
// transposed weights for enc (coalesced float4 over contraction dim)
__device__ float4 g_wT_in[64 * 768];       // [d4*768 + col]
__device__ float4 g_wT_out[64 * 256];
__device__ float4 g_wT_f1[64 * 256];
__device__ float4 g_wT_f2[64 * 256];
__device__ float4 g_wT_dec[64 * 256];

__device__ __forceinline__ float warp_sum(float v) {
    #pragma unroll
    for (int o = 16; o; o >>= 1) v += __shfl_xor_sync(0xffffffffu, v, o);
    return v;
}
__device__ __forceinline__ double warp_sum_d(double v) {
    #pragma unroll
    for (int o = 16; o; o >>= 1) v += __shfl_xor_sync(0xffffffffu, v, o);
    return v;
}

__device__ __forceinline__ uint32_t to_tf32(float f) {
    uint32_t u;
    asm("cvt.rna.tf32.f32 %0, %1;" : "=r"(u) : "f"(f));
    return u;
}

// Kahan compensated add (intrinsics defeat contraction/reassociation)
__device__ __forceinline__ void kadd(float& s, float& c, float v) {
    float y = __fsub_rn(v, c);
    float t = __fadd_rn(s, y);
    c = __fsub_rn(__fsub_rn(t, s), y);
    s = t;
}

// ------------------------------------------------------------- transposes ---
__global__ void __launch_bounds__(256) transW_kernel(
    const float* __restrict__ src, float4* __restrict__ dst, int NC) {
    int idx = blockIdx.x * 256 + threadIdx.x;           // idx = d4*NC + col
    if (idx >= 64 * NC) return;
    int d4 = idx / NC, col = idx % NC;
    const float* p = src + (size_t)col * 256 + 4 * d4;
    dst[idx] = make_float4(p[0], p[1], p[2], p[3]);
}

// keys -> d-major tf32-rounded layout for mma B fragments
__global__ void __launch_bounds__(256) transK_kernel(const float* __restrict__ keys) {
    int idx = blockIdx.x * 256 + threadIdx.x;   // (c*256 + d)*2048 + j
    int j = idx & 2047;
    int d = (idx >> 11) & 255;
    int c = idx >> 19;
    float v = keys[((size_t)(c * PP + j)) * 256 + d];
    g_kTT[idx] = __uint_as_float(to_tf32(v));
}

// ----------------------------------------------------------------- LN -------
__device__ __forceinline__ void ln_rows(float (*src)[DKx], float (*dst)[DKx],
                                        const float* __restrict__ g,
                                        const float* __restrict__ b, int tid) {
    int w = tid >> 5, lane = tid & 31;
    float* row = src[w];
    float s = 0.f;
    #pragma unroll
    for (int k = 0; k < 8; k++) s += row[lane + 32 * k];
    s = warp_sum(s);
    float mu = s * (1.f / 256.f);
    float v = 0.f;
    #pragma unroll
    for (int k = 0; k < 8; k++) { float t = row[lane + 32 * k] - mu; v = fmaf(t, t, v); }
    v = warp_sum(v);
    float rs = 1.0f / sqrtf(v * (1.f / 256.f) + 1e-5f);
    #pragma unroll
    for (int k = 0; k < 8; k++) {
        int d = lane + 32 * k;
        dst[w][d] = (row[d] - mu) * rs * g[d] + b[d];
    }
}

// Compensated 8-row dot: 16-MAC chunks (serial FMA chain), Kahan across chunks.
__device__ __forceinline__ void dot8k(const float4* __restrict__ A4, int stride4,
                                      const float4* __restrict__ wT4, int NC, int col,
                                      float* out) {
    float s[8], c[8];
    #pragma unroll
    for (int l = 0; l < 8; l++) { s[l] = 0.f; c[l] = 0.f; }
    #pragma unroll 2
    for (int g = 0; g < 16; ++g) {
        float4 w0 = __ldg(wT4 + (size_t)(4 * g + 0) * NC + col);
        float4 w1 = __ldg(wT4 + (size_t)(4 * g + 1) * NC + col);
        float4 w2 = __ldg(wT4 + (size_t)(4 * g + 2) * NC + col);
        float4 w3 = __ldg(wT4 + (size_t)(4 * g + 3) * NC + col);
        #pragma unroll
        for (int l = 0; l < 8; l++) {
            const float4 a0 = A4[l * stride4 + 4 * g + 0];
            const float4 a1 = A4[l * stride4 + 4 * g + 1];
            const float4 a2 = A4[l * stride4 + 4 * g + 2];
            const float4 a3 = A4[l * stride4 + 4 * g + 3];
            float ch = a0.x * w0.x;
            ch = fmaf(a0.y, w0.y, ch); ch = fmaf(a0.z, w0.z, ch); ch = fmaf(a0.w, w0.w, ch);
            ch = fmaf(a1.x, w1.x, ch); ch = fmaf(a1.y, w1.y, ch);
            ch = fmaf(a1.z, w1.z, ch); ch = fmaf(a1.w, w1.w, ch);
            ch = fmaf(a2.x, w2.x, ch); ch = fmaf(a2.y, w2.y, ch);
            ch = fmaf(a2.z, w2.z, ch); ch = fmaf(a2.w, w2.w, ch);
            ch = fmaf(a3.x, w3.x, ch); ch = fmaf(a3.y, w3.y, ch);
            ch = fmaf(a3.z, w3.z, ch); ch = fmaf(a3.w, w3.w, ch);
            kadd(s[l], c[l], ch);
        }
    }
    #pragma unroll
    for (int l = 0; l < 8; l++) out[l] = __fadd_rn(s[l], c[l]);
}

// ---------------------------------------------------------------- Kernel A ---
__global__ void __launch_bounds__(256) enc_kernel(
    const float* __restrict__ x,
    const float* __restrict__ ln1_g, const float* __restrict__ ln1_b,
    const float* __restrict__ b_in,  const float* __restrict__ b_out,
    const float* __restrict__ ln2_g, const float* __restrict__ ln2_b,
    const float* __restrict__ fb1,   const float* __restrict__ fb2,
    const float* __restrict__ db,
    float* __restrict__ out_flat)
{
    __shared__ __align__(16) float flat_s[8][DKx];
    __shared__ __align__(16) float a_s[8][DKx];
    __shared__ __align__(16) float qkv_s[8][768];
    __shared__ float sc[2][8][8];

    int i = blockIdx.x, tid = threadIdx.x;

    for (int idx = tid; idx < 2048; idx += 256)
        flat_s[idx >> 8][idx & 255] = x[((size_t)i * 8 + (idx >> 8)) * 256 + (idx & 255)];
    __syncthreads();

    ln_rows(flat_s, a_s, ln1_g, ln1_b, tid);
    __syncthreads();

    // qkv = h0 @ w_in^T + b_in
    for (int ch = 0; ch < 3; ++ch) {
        int col = ch * 256 + tid;
        float res[8];
        dot8k((const float4*)&a_s[0][0], 64, g_wT_in, 768, col, res);
        float bi = b_in[col];
        #pragma unroll
        for (int l = 0; l < 8; l++) qkv_s[l][col] = __fadd_rn(res[l], bi);
    }
    __syncthreads();

    // scores (fp32, 4-way split accumulators)
    if (tid < 128) {
        int h = tid >> 6, rem = tid & 63, l = rem >> 3, m = rem & 7;
        const float* q  = &qkv_s[l][h * 128];
        const float* kk = &qkv_s[m][256 + h * 128];
        float a0 = 0.f, a1 = 0.f, a2 = 0.f, a3 = 0.f;
        #pragma unroll 8
        for (int d = 0; d < 128; d += 4) {
            a0 = fmaf(q[d],     kk[d],     a0);
            a1 = fmaf(q[d + 1], kk[d + 1], a1);
            a2 = fmaf(q[d + 2], kk[d + 2], a2);
            a3 = fmaf(q[d + 3], kk[d + 3], a3);
        }
        float s = __fadd_rn(__fadd_rn(a0, a1), __fadd_rn(a2, a3));
        sc[h][l][m] = s / 11.313708498984760f;
    }
    __syncthreads();

    // softmax
    if (tid < 16) {
        int h = tid >> 3, l = tid & 7;
        float* row = sc[h][l];
        float mx = row[0];
        #pragma unroll
        for (int m = 1; m < 8; m++) mx = fmaxf(mx, row[m]);
        float e[8], sm = 0.f;
        #pragma unroll
        for (int m = 0; m < 8; m++) { e[m] = expf(row[m] - mx); sm += e[m]; }
        float inv = 1.f / sm;
        #pragma unroll
        for (int m = 0; m < 8; m++) row[m] = e[m] * inv;
    }
    __syncthreads();

    // o = a @ v
    {
        int e = tid, h = e >> 7;
        #pragma unroll
        for (int l = 0; l < 8; l++) {
            float s = 0.f;
            #pragma unroll
            for (int m = 0; m < 8; m++) s = fmaf(sc[h][l][m], qkv_s[m][512 + e], s);
            a_s[l][e] = s;
        }
    }
    __syncthreads();

    // proj + residual
    {
        int col = tid;
        float res[8];
        dot8k((const float4*)&a_s[0][0], 64, g_wT_out, 256, col, res);
        float bo = b_out[col];
        #pragma unroll
        for (int l = 0; l < 8; l++)
            flat_s[l][col] = __fadd_rn(__fadd_rn(res[l], bo), flat_s[l][col]);
    }
    __syncthreads();

    ln_rows(flat_s, a_s, ln2_g, ln2_b, tid);
    __syncthreads();

    // ffn1 + gelu (exact, fp32 erff)
    {
        int col = tid;
        float res[8];
        dot8k((const float4*)&a_s[0][0], 64, g_wT_f1, 256, col, res);
        float b1 = fb1[col];
        #pragma unroll
        for (int l = 0; l < 8; l++) {
            float u = __fadd_rn(res[l], b1);
            qkv_s[l][col] = 0.5f * u * (1.0f + erff(u * 0.70710678118654752f));
        }
    }
    __syncthreads();

    // ffn2 + residual
    {
        int col = tid;
        float res[8];
        dot8k((const float4*)&qkv_s[0][0], 192, g_wT_f2, 256, col, res);
        float b2 = fb2[col];
        #pragma unroll
        for (int l = 0; l < 8; l++)
            flat_s[l][col] = __fadd_rn(__fadd_rn(res[l], b2), flat_s[l][col]);
    }
    __syncthreads();

    // dec -> flatten
    {
        int col = tid;
        float res[8];
        dot8k((const float4*)&flat_s[0][0], 64, g_wT_dec, 256, col, res);
        float bd = db[col];
        #pragma unroll
        for (int l = 0; l < 8; l++)
            out_flat[((size_t)l * BB + i) * 256 + col] = __fadd_rn(res[l], bd);
    }
}

// ---------------------------------------------------------------- knorm ------
__global__ void __launch_bounds__(256) knorm_kernel(const float* __restrict__ keys) {
    int gw = (blockIdx.x * 256 + threadIdx.x) >> 5;
    int lane = threadIdx.x & 31;
    if (gw >= CB * PP) return;
    const float* row = keys + (size_t)gw * 256;
    float s = 0.f;
    #pragma unroll
    for (int k = 0; k < 8; k++) { float t = row[lane + 32 * k]; s = fmaf(t, t, s); }
    s = warp_sum(s);
    if (lane == 0) g_knorm[gw] = s;
}

// ---------------------------------------------------------------- Kernel B ---
// tf32 tensor-core distance GEMM + hierarchical top-k shortlist.
// CTA: 16 tokens x 2048 keys, 8 warps; warp covers 64 cols per 512-col tile.
__device__ __forceinline__ void ins8(float (&tv)[NTL], int (&ti)[NTL], float v, int j) {
    if (v > tv[NTL - 1]) {
        tv[NTL - 1] = v; ti[NTL - 1] = j;
        #pragma unroll
        for (int p = NTL - 1; p > 0; --p) {
            if (tv[p] > tv[p - 1]) {
                float a = tv[p]; tv[p] = tv[p - 1]; tv[p - 1] = a;
                int   b = ti[p]; ti[p] = ti[p - 1]; ti[p - 1] = b;
            }
        }
    }
}

__global__ void __launch_bounds__(256) dist_kernel(const float* __restrict__ flat)
{
    __shared__ float F[16][260];
    __shared__ float mv[16][256];
    __shared__ unsigned short mi[16][256];

    int c = blockIdx.y, ib = blockIdx.x, tid = threadIdx.x;
    int i0 = ib * 16;
    int w = tid >> 5, lane = tid & 31;
    int r = lane >> 2, q4 = lane & 3;

    for (int idx = tid; idx < 4096; idx += 256) {
        int rr = idx >> 8, d = idx & 255;
        F[rr][d] = flat[((size_t)c * BB + i0 + rr) * 256 + d];
    }
    __syncthreads();

    float tvA[NTL], tvB[NTL];
    int   tiA[NTL], tiB[NTL];
    #pragma unroll
    for (int t = 0; t < NTL; ++t) {
        tvA[t] = -1e30f; tvB[t] = -1e30f; tiA[t] = 0; tiB[t] = 0;
    }

    const float* KT = g_kTT + (size_t)c * 256 * PP;
    const float* kn = g_knorm + c * PP;

    for (int tile = 0; tile < 4; ++tile) {
        int jw = tile * 512 + w * 64;
        float C[8][4];
        #pragma unroll
        for (int nt = 0; nt < 8; ++nt)
            { C[nt][0] = 0.f; C[nt][1] = 0.f; C[nt][2] = 0.f; C[nt][3] = 0.f; }

        for (int k8 = 0; k8 < 32; ++k8) {
            int kb = k8 * 8;
            uint32_t a0 = to_tf32(F[r][kb + q4]);
            uint32_t a1 = to_tf32(F[r + 8][kb + q4]);
            uint32_t a2 = to_tf32(F[r][kb + 4 + q4]);
            uint32_t a3 = to_tf32(F[r + 8][kb + 4 + q4]);
            #pragma unroll
            for (int nt = 0; nt < 8; ++nt) {
                int jb = jw + nt * 8;
                uint32_t b0 = __float_as_uint(__ldg(KT + (size_t)(kb + q4) * PP + jb + r));
                uint32_t b1 = __float_as_uint(__ldg(KT + (size_t)(kb + 4 + q4) * PP + jb + r));
                asm volatile(
                    "mma.sync.aligned.m16n8k8.row.col.f32.tf32.tf32.f32 "
                    "{%0,%1,%2,%3}, {%4,%5,%6,%7}, {%8,%9}, {%0,%1,%2,%3};\n"
                    : "+f"(C[nt][0]), "+f"(C[nt][1]), "+f"(C[nt][2]), "+f"(C[nt][3])
                    : "r"(a0), "r"(a1), "r"(a2), "r"(a3), "r"(b0), "r"(b1));
            }
        }

        // scores + per-thread shortlist (ascending j => stable tie order)
        #pragma unroll
        for (int nt = 0; nt < 8; ++nt) {
            int j0 = jw + nt * 8 + 2 * q4;
            float kn0 = __ldg(kn + j0), kn1 = __ldg(kn + j0 + 1);
            ins8(tvA, tiA, fmaf(2.f, C[nt][0], -kn0), j0);
            ins8(tvA, tiA, fmaf(2.f, C[nt][1], -kn1), j0 + 1);
            ins8(tvB, tiB, fmaf(2.f, C[nt][2], -kn0), j0);
            ins8(tvB, tiB, fmaf(2.f, C[nt][3], -kn1), j0 + 1);
        }
    }

    // dump per-thread lists: row r gets 32 lists (8 warps x 4 q4) of NTL entries
    int slot = (w * 4 + q4) * NTL;
    #pragma unroll
    for (int t = 0; t < NTL; ++t) {
        mv[r][slot + t] = tvA[t];     mi[r][slot + t] = (unsigned short)tiA[t];
        mv[r + 8][slot + t] = tvB[t]; mi[r + 8][slot + t] = (unsigned short)tiB[t];
    }
    __syncthreads();

    // merge 256 entries per row -> top NSHORT (tie-break: lower index)
    if (tid < 16) {
        int row = tid;
        float fv[NSHORT];
        int   fi[NSHORT];
        #pragma unroll
        for (int t = 0; t < NSHORT; ++t) { fv[t] = -1e30f; fi[t] = 0x7fffffff; }
        for (int e = 0; e < 256; ++e) {
            float v = mv[row][e];
            int jj = (int)mi[row][e];
            if (v > fv[NSHORT - 1] || (v == fv[NSHORT - 1] && jj < fi[NSHORT - 1])) {
                fv[NSHORT - 1] = v; fi[NSHORT - 1] = jj;
                #pragma unroll
                for (int p = NSHORT - 1; p > 0; --p) {
                    if (fv[p] > fv[p - 1] || (fv[p] == fv[p - 1] && fi[p] < fi[p - 1])) {
                        float a = fv[p]; fv[p] = fv[p - 1]; fv[p - 1] = a;
                        int   b = fi[p]; fi[p] = fi[p - 1]; fi[p - 1] = b;
                    }
                }
            }
        }
        int ig = i0 + row;
        #pragma unroll
        for (int t = 0; t < NSHORT; ++t)
            g_short[((size_t)ig * 8 + c) * NSHORT + t] = fi[t];
    }
}

// ---------------------------------------------------------------- refine -----
// fp64 exact terms + fp32 tensor-boundary emulation of the reference dist,
// tie-break by lower index (jax.lax.top_k).
__global__ void __launch_bounds__(256) refine_kernel(
    const float* __restrict__ flat, const float* __restrict__ keys,
    const float* __restrict__ counter, float* __restrict__ out)
{
    int gw = (blockIdx.x * 256 + threadIdx.x) >> 5;   // row = i*8 + c
    int lane = threadIdx.x & 31;
    if (gw >= BB * CB) return;
    int i = gw >> 3, c = gw & 7;

    const float* frow = flat + ((size_t)c * BB + i) * 256;
    double f[8];
    double fn = 0.0;
    #pragma unroll
    for (int k = 0; k < 8; k++) {
        f[k] = (double)frow[lane + 32 * k];
        fn += f[k] * f[k];
    }
    fn = warp_sum_d(fn);

    float sv[NSHORT];
    int   si[NSHORT];
    float A32 = (float)fn;
    #pragma unroll
    for (int t = 0; t < NSHORT; ++t) {
        int idx = g_short[(size_t)gw * NSHORT + t];
        si[t] = idx;
        const float* krow = keys + ((size_t)c * PP + idx) * 256;
        double dot = 0.0, kn = 0.0;
        #pragma unroll
        for (int k = 0; k < 8; k++) {
            double kd = (double)krow[lane + 32 * k];
            dot += f[k] * kd;
            kn  += kd * kd;
        }
        dot = warp_sum_d(dot);
        kn  = warp_sum_d(kn);
        float B32 = 2.0f * (float)dot;
        float C32 = (float)kn;
        float t1  = __fadd_rn(A32, -B32);
        float t2  = __fadd_rn(t1, C32);
        sv[t] = -t2;
    }

    if (lane == 0) {
        #pragma unroll
        for (int a = 0; a < TK; ++a) {
            int best = a;
            #pragma unroll
            for (int b2 = a + 1; b2 < NSHORT; ++b2) {
                if (sv[b2] > sv[best] || (sv[b2] == sv[best] && si[b2] < si[best]))
                    best = b2;
            }
            float vtmp = sv[a]; sv[a] = sv[best]; sv[best] = vtmp;
            int   itmp = si[a]; si[a] = si[best]; si[best] = itmp;
            size_t o = ((size_t)i * 8 + c) * 4 + a;
            out[OFF_IND + o]  = (float)si[a];
            out[OFF_DIST + o] = sv[a];
            out[OFF_CNT + o]  = counter[c * PP + si[a]];
            g_idx[o] = si[a];
        }
    }
}

// ---------------------------------------------------------------- Kernel C ---
__global__ void __launch_bounds__(256) gather_kernel(
    const float* __restrict__ keys, const float* __restrict__ values,
    float* __restrict__ out)
{
    int gw = (blockIdx.x * 256 + threadIdx.x) >> 5;
    int lane = threadIdx.x & 31;
    int c = (gw >> 2) & 7;
    int idx = g_idx[gw];
    const float4* ks = (const float4*)(keys   + ((size_t)c * PP + idx) * 256);
    const float4* vs = (const float4*)(values + ((size_t)c * PP + idx) * 256);
    float4* oqk = (float4*)(out + OFF_QK) + (size_t)gw * 64;
    float4* oqv = (float4*)(out + OFF_QV) + (size_t)gw * 64;
    oqv[lane]      = vs[lane];
    oqv[lane + 32] = vs[lane + 32];
    oqk[lane]      = ks[lane];
    oqk[lane + 32] = ks[lane + 32];
}

// -----------------------------------------------------------------------------
extern "C" void kernel_launch(void* const* d_in, const int* in_sizes, int n_in,
                              void* d_out, int out_size) {
    const float* x       = (const float*)d_in[0];
    const float* keys    = (const float*)d_in[1];
    const float* values  = (const float*)d_in[2];
    const float* counter = (const float*)d_in[3];
    const float* ln1_g   = (const float*)d_in[4];
    const float* ln1_b   = (const float*)d_in[5];
    const float* w_in    = (const float*)d_in[6];
    const float* b_in    = (const float*)d_in[7];
    const float* w_out   = (const float*)d_in[8];
    const float* b_out   = (const float*)d_in[9];
    const float* ln2_g   = (const float*)d_in[10];
    const float* ln2_b   = (const float*)d_in[11];
    const float* fw1     = (const float*)d_in[12];
    const float* fb1     = (const float*)d_in[13];
    const float* fw2     = (const float*)d_in[14];
    const float* fb2     = (const float*)d_in[15];
    const float* dw      = (const float*)d_in[16];
    const float* db      = (const float*)d_in[17];
    float* out = (float*)d_out;

    float4* wt_in;  cudaGetSymbolAddress((void**)&wt_in,  g_wT_in);
    float4* wt_out; cudaGetSymbolAddress((void**)&wt_out, g_wT_out);
    float4* wt_f1;  cudaGetSymbolAddress((void**)&wt_f1,  g_wT_f1);
    float4* wt_f2;  cudaGetSymbolAddress((void**)&wt_f2,  g_wT_f2);
    float4* wt_dec; cudaGetSymbolAddress((void**)&wt_dec, g_wT_dec);

    transW_kernel<<<(64 * 768 + 255) / 256, 256>>>(w_in,  wt_in,  768);
    transW_kernel<<<(64 * 256 + 255) / 256, 256>>>(w_out, wt_out, 256);
    transW_kernel<<<(64 * 256 + 255) / 256, 256>>>(fw1,   wt_f1,  256);
    transW_kernel<<<(64 * 256 + 255) / 256, 256>>>(fw2,   wt_f2,  256);
    transW_kernel<<<(64 * 256 + 255) / 256, 256>>>(dw,    wt_dec, 256);
    transK_kernel<<<CB * 256 * PP / 256, 256>>>(keys);
    knorm_kernel<<<2048, 256>>>(keys);

    enc_kernel<<<BB, 256>>>(x, ln1_g, ln1_b, b_in, b_out,
                            ln2_g, ln2_b, fb1, fb2, db, out + OFF_FLAT);
    dist_kernel<<<dim3(BB / 16, CB), 256>>>(out + OFF_FLAT);
    refine_kernel<<<BB * CB / 8, 256>>>(out + OFF_FLAT, keys, counter, out);
    gather_kernel<<<32768, 256>>>(keys, values, out);
}